// round 4
// baseline (speedup 1.0000x reference)
#include <cuda_runtime.h>
#include <cstdint>

#define NN 50000
#define NE 1600000
#define D  128
#define C  21
#define RP 32    // padded table row stride (floats) -> 128B line-aligned
#define WR 132   // transposed weight row stride (floats); 132/4=33 ≡ 1 (mod 32)

// Scratch in __device__ globals (no cudaMalloc allowed).
__device__ float g_WcT[2][C][WR];                 // fused weights, transposed [table][class][k]
__device__ float g_cvec[C];                       // b_fuse@Wcls + b_cls
__device__ __align__(128) float g_Asrc[NN][RP];   // emb @ Wc[0] + cvec
__device__ __align__(128) float g_Adst[NN][RP];   // emb @ Wc[1]
__device__ int  g_is64;
__device__ __align__(16) int2 g_sd[NE];           // packed (src,dst) int32

// --------------------------------------------------------------------------
// Kernel 0: detect edge_index dtype (int32 reinterpreted as int64 is huge whp)
// --------------------------------------------------------------------------
__global__ void detect_dtype_kernel(const long long* __restrict__ ei) {
    if (threadIdx.x == 0) {
        bool ok64 = true;
        #pragma unroll
        for (int k = 0; k < 4; k++) {
            long long v = ei[k];
            if (v < 0 || v >= NN) ok64 = false;
        }
        g_is64 = ok64 ? 1 : 0;
    }
}

// --------------------------------------------------------------------------
// Kernel 0b: convert + pack indices into int2
// --------------------------------------------------------------------------
__global__ __launch_bounds__(256) void convert_idx_kernel(const void* __restrict__ eiv) {
    unsigned e = blockIdx.x * 256u + threadIdx.x;
    if (e >= NE) return;
    int s, d;
    if (g_is64) {
        const long long* ei = (const long long*)eiv;
        s = (int)ei[e];
        d = (int)ei[NE + e];
    } else {
        const int* ei = (const int*)eiv;
        s = ei[e];
        d = ei[NE + e];
    }
    g_sd[e] = make_int2(s, d);
}

// --------------------------------------------------------------------------
// Kernel 1: fold [D,D] fuse weights through classifier -> transposed [C][D]
// (rows padded to WR=132, pad zeroed). Tiny.
// --------------------------------------------------------------------------
__global__ void fuse_weights_kernel(const float* __restrict__ Wsrc,
                                    const float* __restrict__ Wdst,
                                    const float* __restrict__ bfuse,
                                    const float* __restrict__ Wcls,
                                    const float* __restrict__ bcls) {
    int i = blockIdx.x * blockDim.x + threadIdx.x;
    if (i < 2 * C * WR) {
        int which = i / (C * WR);
        int rem   = i - which * (C * WR);
        int c = rem / WR;
        int r = rem - c * WR;
        float acc = 0.f;
        if (r < D) {
            const float* W = which ? Wdst : Wsrc;
            #pragma unroll 16
            for (int j = 0; j < D; j++)
                acc += W[r * D + j] * Wcls[j * C + c];
        }
        g_WcT[which][c][r] = acc;
    } else if (i < 2 * C * WR + C) {
        int c = i - 2 * C * WR;
        float acc = bcls[c];
        for (int j = 0; j < D; j++)
            acc += bfuse[j] * Wcls[j * C + c];
        g_cvec[c] = acc;
    }
}

// --------------------------------------------------------------------------
// Kernel 2: per-node projection tables. 32 nodes/block, 4 nodes/thread,
// all-float4 shared loads (weights transposed, lane stride 33 float4 -> no
// bank conflicts; x loads broadcast).
// --------------------------------------------------------------------------
__global__ __launch_bounds__(256) void node_proj_kernel(const float* __restrict__ emb) {
    __shared__ float sWT[2][C][WR];   // 22176 B
    __shared__ float sx[32][D];       // 16384 B

    int tid = threadIdx.y * 32 + threadIdx.x;

    // stage transposed weights (5544 floats = 1386 float4)
    const float4* gW4 = (const float4*)&g_WcT[0][0][0];
    float4* sW4 = (float4*)&sWT[0][0][0];
    for (int i = tid; i < 2 * C * WR / 4; i += 256)
        sW4[i] = gW4[i];

    // stage 32 embedding rows (1024 float4)
    int node0 = blockIdx.x * 32;
    const float4* emb4 = (const float4*)emb;
    float4* sx4 = (float4*)&sx[0][0];
    for (int i = tid; i < 32 * D / 4; i += 256) {
        int n = node0 + (i >> 5);
        sx4[i] = (n < NN) ? emb4[(size_t)n * (D / 4) + (i & 31)]
                          : make_float4(0.f, 0.f, 0.f, 0.f);
    }
    __syncthreads();

    int c = threadIdx.x;
    int r = threadIdx.y;
    if (c < C) {
        const float4* w0p = (const float4*)sWT[0][c];
        const float4* w1p = (const float4*)sWT[1][c];
        const float4* x0p = (const float4*)sx[r];
        const float4* x1p = (const float4*)sx[r + 8];
        const float4* x2p = (const float4*)sx[r + 16];
        const float4* x3p = (const float4*)sx[r + 24];
        float a0 = 0.f, a1 = 0.f, a2 = 0.f, a3 = 0.f;
        float b0 = 0.f, b1 = 0.f, b2 = 0.f, b3 = 0.f;
        #pragma unroll 8
        for (int kk = 0; kk < D / 4; kk++) {
            float4 w0 = w0p[kk];
            float4 w1 = w1p[kk];
            float4 x0 = x0p[kk];
            float4 x1 = x1p[kk];
            float4 x2 = x2p[kk];
            float4 x3 = x3p[kk];
            a0 += x0.x*w0.x + x0.y*w0.y + x0.z*w0.z + x0.w*w0.w;
            b0 += x0.x*w1.x + x0.y*w1.y + x0.z*w1.z + x0.w*w1.w;
            a1 += x1.x*w0.x + x1.y*w0.y + x1.z*w0.z + x1.w*w0.w;
            b1 += x1.x*w1.x + x1.y*w1.y + x1.z*w1.z + x1.w*w1.w;
            a2 += x2.x*w0.x + x2.y*w0.y + x2.z*w0.z + x2.w*w0.w;
            b2 += x2.x*w1.x + x2.y*w1.y + x2.z*w1.z + x2.w*w1.w;
            a3 += x3.x*w0.x + x3.y*w0.y + x3.z*w0.z + x3.w*w0.w;
            b3 += x3.x*w1.x + x3.y*w1.y + x3.z*w1.z + x3.w*w1.w;
        }
        float cv = g_cvec[c];
        int n0 = node0 + r;
        if (n0      < NN) { g_Asrc[n0][c]      = a0 + cv; g_Adst[n0][c]      = b0; }
        if (n0 + 8  < NN) { g_Asrc[n0 + 8][c]  = a1 + cv; g_Adst[n0 + 8][c]  = b1; }
        if (n0 + 16 < NN) { g_Asrc[n0 + 16][c] = a2 + cv; g_Adst[n0 + 16][c] = b2; }
        if (n0 + 24 < NN) { g_Asrc[n0 + 24][c] = a3 + cv; g_Adst[n0 + 24][c] = b3; }
    }
}

// --------------------------------------------------------------------------
// Kernel 3: warp-cooperative gather. Lane = class; each warp handles 4 edges
// with 2 broadcast int4 index loads + 8 independent single-line row gathers.
// --------------------------------------------------------------------------
__global__ __launch_bounds__(256) void edge_out_kernel(float* __restrict__ out) {
    unsigned warp = (blockIdx.x * 256u + threadIdx.x) >> 5;
    int lane = threadIdx.x & 31;
    unsigned e0 = warp * 4u;
    if (e0 >= NE) return;

    const int4* sd4 = (const int4*)g_sd;
    int4 p0 = __ldg(&sd4[e0 >> 1]);        // (s0,d0,s1,d1)
    int4 p1 = __ldg(&sd4[(e0 >> 1) + 1]);  // (s2,d2,s3,d3)

    // lanes 21..31 read in-row padding (rows are RP=32 wide) -> safe
    float v0 = g_Asrc[p0.x][lane] + g_Adst[p0.y][lane];
    float v1 = g_Asrc[p0.z][lane] + g_Adst[p0.w][lane];
    float v2 = g_Asrc[p1.x][lane] + g_Adst[p1.y][lane];
    float v3 = g_Asrc[p1.z][lane] + g_Adst[p1.w][lane];

    if (lane < C) {
        unsigned b = e0 * C;
        out[b + lane]         = v0;
        out[b + C + lane]     = v1;
        out[b + 2 * C + lane] = v2;
        out[b + 3 * C + lane] = v3;
    }
}

// --------------------------------------------------------------------------
extern "C" void kernel_launch(void* const* d_in, const int* in_sizes, int n_in,
                              void* d_out, int out_size) {
    const float* emb  = nullptr;
    const void*  ei   = nullptr;
    const float* Wsrc = nullptr;
    const float* Wdst = nullptr;
    const float* bf   = nullptr;
    const float* Wcls = nullptr;
    const float* bcls = nullptr;
    for (int k = 0; k < n_in; k++) {
        switch (in_sizes[k]) {
            case NN * D: emb = (const float*)d_in[k]; break;
            case 2 * NE: ei  = d_in[k];               break;
            case D * D:  if (!Wsrc) Wsrc = (const float*)d_in[k];
                         else       Wdst = (const float*)d_in[k];
                         break;
            case D:      bf   = (const float*)d_in[k]; break;
            case D * C:  Wcls = (const float*)d_in[k]; break;
            case C:      bcls = (const float*)d_in[k]; break;
            default: break;
        }
    }
    float* out = (float*)d_out;

    detect_dtype_kernel<<<1, 32>>>((const long long*)ei);
    convert_idx_kernel<<<(NE + 255) / 256, 256>>>(ei);
    fuse_weights_kernel<<<(2 * C * WR + C + 255) / 256, 256>>>(Wsrc, Wdst, bf, Wcls, bcls);
    node_proj_kernel<<<(NN + 31) / 32, dim3(32, 8)>>>(emb);

    // one warp per 4 edges: NE/4 = 400000 warps = 50000 blocks of 256
    edge_out_kernel<<<NE / 4 / 8, 256>>>(out);
}